// round 1
// baseline (speedup 1.0000x reference)
#include <cuda_runtime.h>

#define NUM_USERS 100000
#define NUM_ITEMS 200000
#define NNODES    300000
#define EMB       64
#define NNZ_C     10000000
#define BATCH     8192

// Ping-pong layer buffers + accumulator. float4 arrays guarantee 16B alignment
// for red.global.add.v4.f32. Each is 300000*64 floats = 76.8 MB.
__device__ float4 g_xA[(size_t)NNODES * 16];
__device__ float4 g_xB[(size_t)NNODES * 16];
__device__ float4 g_acc[(size_t)NNODES * 16];

// x0 = concat(user_emb, item_emb); acc = x0; zero the first destination buffer.
__global__ void init_kernel(const float4* __restrict__ ue, const float4* __restrict__ ie) {
    size_t i = (size_t)blockIdx.x * blockDim.x + threadIdx.x;
    const size_t total = (size_t)NNODES * 16;
    if (i >= total) return;
    const size_t usplit = (size_t)NUM_USERS * 16;
    float4 v = (i < usplit) ? ue[i] : ie[i - usplit];
    g_xA[i] = v;
    g_acc[i] = v;
    g_xB[i] = make_float4(0.f, 0.f, 0.f, 0.f);
}

// COO SpMM: 16 threads per edge, one float4 per lane.
// Gather x[col] (coalesced 256B per edge), scale by val, vector-reduce into xn[row].
__global__ void __launch_bounds__(256) spmm_kernel(
    const float4* __restrict__ x, float4* __restrict__ xn,
    const float* __restrict__ vals, const int* __restrict__ rows,
    const int* __restrict__ cols)
{
    long long t = (long long)blockIdx.x * blockDim.x + threadIdx.x;
    int e = (int)(t >> 4);
    if (e >= NNZ_C) return;
    int lane = (int)(t & 15);

    int   r = __ldg(rows + e);
    int   c = __ldg(cols + e);
    float v = __ldg(vals + e);

    float4 m = __ldg(x + (size_t)c * 16 + lane);
    float4* dst = xn + (size_t)r * 16 + lane;
    asm volatile("red.global.add.v4.f32 [%0], {%1,%2,%3,%4};"
                 :: "l"(dst), "f"(m.x * v), "f"(m.y * v), "f"(m.z * v), "f"(m.w * v)
                 : "memory");
}

// acc += layer output; zero the buffer that will be the NEXT layer's destination.
__global__ void post_kernel(const float4* __restrict__ xdst, float4* __restrict__ xsrc_zero) {
    size_t i = (size_t)blockIdx.x * blockDim.x + threadIdx.x;
    const size_t total = (size_t)NNODES * 16;
    if (i >= total) return;
    float4 a = g_acc[i];
    float4 d = xdst[i];
    a.x += d.x; a.y += d.y; a.z += d.z; a.w += d.w;
    g_acc[i] = a;
    xsrc_zero[i] = make_float4(0.f, 0.f, 0.f, 0.f);
}

// One warp per (u, i) pair: 32 lanes x float2 = 64 dims; shuffle reduce.
// out = (acc_u/4) . (acc_i/4) = dot(acc_u, acc_i) / 16.
__global__ void dot_kernel(const int* __restrict__ u, const int* __restrict__ it,
                           float* __restrict__ out)
{
    int w = (int)(((size_t)blockIdx.x * blockDim.x + threadIdx.x) >> 5);
    int lane = threadIdx.x & 31;
    if (w >= BATCH) return;

    int ui = __ldg(u + w);
    int ii = __ldg(it + w) + NUM_USERS;

    const float* a = (const float*)g_acc;
    float2 p = ((const float2*)(a + (size_t)ui * EMB))[lane];
    float2 q = ((const float2*)(a + (size_t)ii * EMB))[lane];
    float s = p.x * q.x + p.y * q.y;

    #pragma unroll
    for (int off = 16; off > 0; off >>= 1)
        s += __shfl_xor_sync(0xFFFFFFFFu, s, off);

    if (lane == 0) out[w] = s * 0.0625f;
}

extern "C" void kernel_launch(void* const* d_in, const int* in_sizes, int n_in,
                              void* d_out, int out_size)
{
    const float4* ue   = (const float4*)d_in[0];
    const float4* ie   = (const float4*)d_in[1];
    const float*  vals = (const float*)d_in[2];
    const int*    rows = (const int*)d_in[3];
    const int*    cols = (const int*)d_in[4];
    const int*    uidx = (const int*)d_in[5];
    const int*    iidx = (const int*)d_in[6];
    float*        out  = (float*)d_out;

    float4 *xA, *xB;
    cudaGetSymbolAddress((void**)&xA, g_xA);
    cudaGetSymbolAddress((void**)&xB, g_xB);

    const size_t total = (size_t)NNODES * 16;
    const int eb = (int)((total + 255) / 256);

    const long long sthreads = (long long)NNZ_C * 16;
    const int sblocks = (int)((sthreads + 255) / 256);

    init_kernel<<<eb, 256>>>(ue, ie);

    // Layer 0: A -> B, then acc += B, zero A (next dst)
    spmm_kernel<<<sblocks, 256>>>(xA, xB, vals, rows, cols);
    post_kernel<<<eb, 256>>>(xB, xA);

    // Layer 1: B -> A, then acc += A, zero B (next dst)
    spmm_kernel<<<sblocks, 256>>>(xB, xA, vals, rows, cols);
    post_kernel<<<eb, 256>>>(xA, xB);

    // Layer 2: A -> B, then acc += B, zero A (determinism across graph replays)
    spmm_kernel<<<sblocks, 256>>>(xA, xB, vals, rows, cols);
    post_kernel<<<eb, 256>>>(xB, xA);

    dot_kernel<<<BATCH / 8, 256>>>(uidx, iidx, out);
}

// round 2
// speedup vs baseline: 1.7122x; 1.7122x over previous
#include <cuda_runtime.h>

#define NUM_USERS 100000
#define NUM_ITEMS 200000
#define NNODES    300000
#define EMB       64
#define NNZ_C     10000000
#define BATCH     8192
#define MASK_WORDS ((NNODES + 31) / 32)

// Per-layer output buffers (76.8 MB each). float4 => 16B alignment for red.v4.f32.
__device__ float4 g_x1[(size_t)NNODES * 16];
__device__ float4 g_x2[(size_t)NNODES * 16];
__device__ float4 g_x3[(size_t)NNODES * 16];
// Bitmap of rows whose layer-3 output is actually consumed by the final dot.
__device__ unsigned g_mask[MASK_WORDS];

__device__ __forceinline__ void red_add_v4(float4* dst, float a, float b, float c, float d) {
    asm volatile("red.global.add.v4.f32 [%0], {%1,%2,%3,%4};"
                 :: "l"(dst), "f"(a), "f"(b), "f"(c), "f"(d) : "memory");
}

// Zero all layer buffers + mask.
__global__ void init_kernel() {
    size_t i = (size_t)blockIdx.x * blockDim.x + threadIdx.x;
    const size_t total = (size_t)NNODES * 16;
    if (i >= total) return;
    float4 z = make_float4(0.f, 0.f, 0.f, 0.f);
    g_x1[i] = z; g_x2[i] = z; g_x3[i] = z;
    if (i < MASK_WORDS) g_mask[i] = 0u;
}

// Set bitmap bits for the 2*BATCH needed rows.
__global__ void mask_set_kernel(const int* __restrict__ u, const int* __restrict__ it) {
    int t = blockIdx.x * blockDim.x + threadIdx.x;
    if (t >= 2 * BATCH) return;
    int r = (t < BATCH) ? __ldg(u + t) : (NUM_USERS + __ldg(it + (t - BATCH)));
    atomicOr(&g_mask[r >> 5], 1u << (r & 31));
}

// Layer 1: gather directly from the two embedding inputs (x0 never materialized).
// 16 lanes per edge, 4 edges per thread for MLP. Block = 256 thr = 16 slots x 16 lanes,
// covering 64 consecutive edges. NNZ = 10M = 64 * 156250 exactly.
__global__ void __launch_bounds__(256) spmm_l1_kernel(
    const float4* __restrict__ ue, const float4* __restrict__ ie,
    float4* __restrict__ xn,
    const float* __restrict__ vals, const int* __restrict__ rows,
    const int* __restrict__ cols)
{
    const int lane = threadIdx.x & 15;
    const int slot = threadIdx.x >> 4;
    const long long base = (long long)blockIdx.x * 64 + slot;

    int   r[4], c[4];
    float v[4];
    #pragma unroll
    for (int j = 0; j < 4; j++) {
        long long e = base + j * 16;
        r[j] = __ldcs(rows + e);
        c[j] = __ldcs(cols + e);
        v[j] = __ldcs(vals + e);
    }
    float4 m[4];
    #pragma unroll
    for (int j = 0; j < 4; j++) {
        const float4* src = (c[j] < NUM_USERS)
            ? (ue + (size_t)c[j] * 16)
            : (ie + (size_t)(c[j] - NUM_USERS) * 16);
        m[j] = __ldg(src + lane);
    }
    #pragma unroll
    for (int j = 0; j < 4; j++) {
        float4* dst = xn + (size_t)r[j] * 16 + lane;
        red_add_v4(dst, m[j].x * v[j], m[j].y * v[j], m[j].z * v[j], m[j].w * v[j]);
    }
}

// Generic dense layer: x -> xn.
__global__ void __launch_bounds__(256) spmm_kernel(
    const float4* __restrict__ x, float4* __restrict__ xn,
    const float* __restrict__ vals, const int* __restrict__ rows,
    const int* __restrict__ cols)
{
    const int lane = threadIdx.x & 15;
    const int slot = threadIdx.x >> 4;
    const long long base = (long long)blockIdx.x * 64 + slot;

    int   r[4], c[4];
    float v[4];
    #pragma unroll
    for (int j = 0; j < 4; j++) {
        long long e = base + j * 16;
        r[j] = __ldcs(rows + e);
        c[j] = __ldcs(cols + e);
        v[j] = __ldcs(vals + e);
    }
    float4 m[4];
    #pragma unroll
    for (int j = 0; j < 4; j++)
        m[j] = __ldg(x + (size_t)c[j] * 16 + lane);
    #pragma unroll
    for (int j = 0; j < 4; j++) {
        float4* dst = xn + (size_t)r[j] * 16 + lane;
        red_add_v4(dst, m[j].x * v[j], m[j].y * v[j], m[j].z * v[j], m[j].w * v[j]);
    }
}

// Layer 3, output-sparse: only edges whose destination row is in the bitmap do work.
__global__ void __launch_bounds__(256) spmm_masked_kernel(
    const float4* __restrict__ x, float4* __restrict__ xn,
    const float* __restrict__ vals, const int* __restrict__ rows,
    const int* __restrict__ cols)
{
    const int lane = threadIdx.x & 15;
    const int slot = threadIdx.x >> 4;
    const long long base = (long long)blockIdx.x * 64 + slot;

    #pragma unroll
    for (int j = 0; j < 4; j++) {
        long long e = base + j * 16;
        int r = __ldcs(rows + e);
        bool need = (__ldg(&g_mask[r >> 5]) >> (r & 31)) & 1u;
        if (need) {
            int   c = __ldg(cols + e);
            float v = __ldg(vals + e);
            float4 m = __ldg(x + (size_t)c * 16 + lane);
            float4* dst = xn + (size_t)r * 16 + lane;
            red_add_v4(dst, m.x * v, m.y * v, m.z * v, m.w * v);
        }
    }
}

// One warp per (u,i) pair. acc_row = x0 + x1 + x2 + x3 formed on the fly.
// out = dot(acc_u, acc_i) / (L+1)^2 = dot / 16.
__global__ void dot_kernel(const float* __restrict__ ue, const float* __restrict__ ie,
                           const int* __restrict__ u, const int* __restrict__ it,
                           float* __restrict__ out)
{
    int w = (int)(((size_t)blockIdx.x * blockDim.x + threadIdx.x) >> 5);
    int lane = threadIdx.x & 31;
    if (w >= BATCH) return;

    int ur = __ldg(u + w);                 // global row = ur (user block)
    int il = __ldg(it + w);
    int ir = NUM_USERS + il;               // global row for item

    const float* x1 = (const float*)g_x1;
    const float* x2 = (const float*)g_x2;
    const float* x3 = (const float*)g_x3;

    float2 p0 = ((const float2*)(ue + (size_t)ur * EMB))[lane];
    float2 p1 = ((const float2*)(x1 + (size_t)ur * EMB))[lane];
    float2 p2 = ((const float2*)(x2 + (size_t)ur * EMB))[lane];
    float2 p3 = ((const float2*)(x3 + (size_t)ur * EMB))[lane];

    float2 q0 = ((const float2*)(ie + (size_t)il * EMB))[lane];
    float2 q1 = ((const float2*)(x1 + (size_t)ir * EMB))[lane];
    float2 q2 = ((const float2*)(x2 + (size_t)ir * EMB))[lane];
    float2 q3 = ((const float2*)(x3 + (size_t)ir * EMB))[lane];

    float px = p0.x + p1.x + p2.x + p3.x;
    float py = p0.y + p1.y + p2.y + p3.y;
    float qx = q0.x + q1.x + q2.x + q3.x;
    float qy = q0.y + q1.y + q2.y + q3.y;

    float s = px * qx + py * qy;
    #pragma unroll
    for (int off = 16; off > 0; off >>= 1)
        s += __shfl_xor_sync(0xFFFFFFFFu, s, off);

    if (lane == 0) out[w] = s * 0.0625f;
}

extern "C" void kernel_launch(void* const* d_in, const int* in_sizes, int n_in,
                              void* d_out, int out_size)
{
    const float4* ue   = (const float4*)d_in[0];
    const float4* ie   = (const float4*)d_in[1];
    const float*  vals = (const float*)d_in[2];
    const int*    rows = (const int*)d_in[3];
    const int*    cols = (const int*)d_in[4];
    const int*    uidx = (const int*)d_in[5];
    const int*    iidx = (const int*)d_in[6];
    float*        out  = (float*)d_out;

    float4 *x1, *x2, *x3;
    cudaGetSymbolAddress((void**)&x1, g_x1);
    cudaGetSymbolAddress((void**)&x2, g_x2);
    cudaGetSymbolAddress((void**)&x3, g_x3);

    const size_t total = (size_t)NNODES * 16;
    const int eb = (int)((total + 255) / 256);
    const int sblocks = NNZ_C / 64;   // 156250, exact

    init_kernel<<<eb, 256>>>();
    mask_set_kernel<<<(2 * BATCH + 255) / 256, 256>>>(uidx, iidx);

    spmm_l1_kernel<<<sblocks, 256>>>(ue, ie, x1, vals, rows, cols);
    spmm_kernel<<<sblocks, 256>>>(x1, x2, vals, rows, cols);
    spmm_masked_kernel<<<sblocks, 256>>>(x2, x3, vals, rows, cols);

    dot_kernel<<<BATCH / 8, 256>>>((const float*)ue, (const float*)ie,
                                   uidx, iidx, out);
}

// round 3
// speedup vs baseline: 1.7313x; 1.0112x over previous
#include <cuda_runtime.h>

#define NUM_USERS 100000
#define NUM_ITEMS 200000
#define NNODES    300000
#define EMB       64
#define NNZ_C     10000000
#define BATCH     8192
#define MASK_WORDS ((NNODES + 31) / 32)

// Per-layer output buffers (76.8 MB each). float4 => 16B alignment for red.v4.f32.
__device__ float4 g_x1[(size_t)NNODES * 16];
__device__ float4 g_x2[(size_t)NNODES * 16];
__device__ float4 g_x3[(size_t)NNODES * 16];
// Bitmap of rows whose layer-3 output is actually consumed by the final dot.
__device__ unsigned g_mask[MASK_WORDS];

__device__ __forceinline__ void red_add_v4(float4* dst, float a, float b, float c, float d) {
    asm volatile("red.global.add.v4.f32 [%0], {%1,%2,%3,%4};"
                 :: "l"(dst), "f"(a), "f"(b), "f"(c), "f"(d) : "memory");
}

// Zero all layer buffers + mask.
__global__ void init_kernel() {
    size_t i = (size_t)blockIdx.x * blockDim.x + threadIdx.x;
    const size_t total = (size_t)NNODES * 16;
    if (i >= total) return;
    float4 z = make_float4(0.f, 0.f, 0.f, 0.f);
    g_x1[i] = z; g_x2[i] = z; g_x3[i] = z;
    if (i < MASK_WORDS) g_mask[i] = 0u;
}

// Set bitmap bits for the 2*BATCH needed rows.
__global__ void mask_set_kernel(const int* __restrict__ u, const int* __restrict__ it) {
    int t = blockIdx.x * blockDim.x + threadIdx.x;
    if (t >= 2 * BATCH) return;
    int r = (t < BATCH) ? __ldg(u + t) : (NUM_USERS + __ldg(it + (t - BATCH)));
    atomicOr(&g_mask[r >> 5], 1u << (r & 31));
}

// Layer 1: gather directly from the two embedding inputs (x0 never materialized).
// 16 lanes per edge, 4 edges per thread for MLP. Block = 256 thr = 16 slots x 16 lanes,
// covering 64 consecutive edges. NNZ = 10M = 64 * 156250 exactly.
__global__ void __launch_bounds__(256) spmm_l1_kernel(
    const float4* __restrict__ ue, const float4* __restrict__ ie,
    float4* __restrict__ xn,
    const float* __restrict__ vals, const int* __restrict__ rows,
    const int* __restrict__ cols)
{
    const int lane = threadIdx.x & 15;
    const int slot = threadIdx.x >> 4;
    const long long base = (long long)blockIdx.x * 64 + slot;

    int   r[4], c[4];
    float v[4];
    #pragma unroll
    for (int j = 0; j < 4; j++) {
        long long e = base + j * 16;
        r[j] = __ldcs(rows + e);
        c[j] = __ldcs(cols + e);
        v[j] = __ldcs(vals + e);
    }
    float4 m[4];
    #pragma unroll
    for (int j = 0; j < 4; j++) {
        const float4* src = (c[j] < NUM_USERS)
            ? (ue + (size_t)c[j] * 16)
            : (ie + (size_t)(c[j] - NUM_USERS) * 16);
        m[j] = __ldg(src + lane);
    }
    #pragma unroll
    for (int j = 0; j < 4; j++) {
        float4* dst = xn + (size_t)r[j] * 16 + lane;
        red_add_v4(dst, m[j].x * v[j], m[j].y * v[j], m[j].z * v[j], m[j].w * v[j]);
    }
}

// Generic dense layer: x -> xn.
__global__ void __launch_bounds__(256) spmm_kernel(
    const float4* __restrict__ x, float4* __restrict__ xn,
    const float* __restrict__ vals, const int* __restrict__ rows,
    const int* __restrict__ cols)
{
    const int lane = threadIdx.x & 15;
    const int slot = threadIdx.x >> 4;
    const long long base = (long long)blockIdx.x * 64 + slot;

    int   r[4], c[4];
    float v[4];
    #pragma unroll
    for (int j = 0; j < 4; j++) {
        long long e = base + j * 16;
        r[j] = __ldcs(rows + e);
        c[j] = __ldcs(cols + e);
        v[j] = __ldcs(vals + e);
    }
    float4 m[4];
    #pragma unroll
    for (int j = 0; j < 4; j++)
        m[j] = __ldg(x + (size_t)c[j] * 16 + lane);
    #pragma unroll
    for (int j = 0; j < 4; j++) {
        float4* dst = xn + (size_t)r[j] * 16 + lane;
        red_add_v4(dst, m[j].x * v[j], m[j].y * v[j], m[j].z * v[j], m[j].w * v[j]);
    }
}

// Layer 3, output-sparse: only edges whose destination row is in the bitmap do work.
__global__ void __launch_bounds__(256) spmm_masked_kernel(
    const float4* __restrict__ x, float4* __restrict__ xn,
    const float* __restrict__ vals, const int* __restrict__ rows,
    const int* __restrict__ cols)
{
    const int lane = threadIdx.x & 15;
    const int slot = threadIdx.x >> 4;
    const long long base = (long long)blockIdx.x * 64 + slot;

    #pragma unroll
    for (int j = 0; j < 4; j++) {
        long long e = base + j * 16;
        int r = __ldcs(rows + e);
        bool need = (__ldg(&g_mask[r >> 5]) >> (r & 31)) & 1u;
        if (need) {
            int   c = __ldg(cols + e);
            float v = __ldg(vals + e);
            float4 m = __ldg(x + (size_t)c * 16 + lane);
            float4* dst = xn + (size_t)r * 16 + lane;
            red_add_v4(dst, m.x * v, m.y * v, m.z * v, m.w * v);
        }
    }
}

// One warp per (u,i) pair. acc_row = x0 + x1 + x2 + x3 formed on the fly.
// out = dot(acc_u, acc_i) / (L+1)^2 = dot / 16.
__global__ void dot_kernel(const float* __restrict__ ue, const float* __restrict__ ie,
                           const int* __restrict__ u, const int* __restrict__ it,
                           float* __restrict__ out)
{
    int w = (int)(((size_t)blockIdx.x * blockDim.x + threadIdx.x) >> 5);
    int lane = threadIdx.x & 31;
    if (w >= BATCH) return;

    int ur = __ldg(u + w);                 // global row = ur (user block)
    int il = __ldg(it + w);
    int ir = NUM_USERS + il;               // global row for item

    const float* x1 = (const float*)g_x1;
    const float* x2 = (const float*)g_x2;
    const float* x3 = (const float*)g_x3;

    float2 p0 = ((const float2*)(ue + (size_t)ur * EMB))[lane];
    float2 p1 = ((const float2*)(x1 + (size_t)ur * EMB))[lane];
    float2 p2 = ((const float2*)(x2 + (size_t)ur * EMB))[lane];
    float2 p3 = ((const float2*)(x3 + (size_t)ur * EMB))[lane];

    float2 q0 = ((const float2*)(ie + (size_t)il * EMB))[lane];
    float2 q1 = ((const float2*)(x1 + (size_t)ir * EMB))[lane];
    float2 q2 = ((const float2*)(x2 + (size_t)ir * EMB))[lane];
    float2 q3 = ((const float2*)(x3 + (size_t)ir * EMB))[lane];

    float px = p0.x + p1.x + p2.x + p3.x;
    float py = p0.y + p1.y + p2.y + p3.y;
    float qx = q0.x + q1.x + q2.x + q3.x;
    float qy = q0.y + q1.y + q2.y + q3.y;

    float s = px * qx + py * qy;
    #pragma unroll
    for (int off = 16; off > 0; off >>= 1)
        s += __shfl_xor_sync(0xFFFFFFFFu, s, off);

    if (lane == 0) out[w] = s * 0.0625f;
}

extern "C" void kernel_launch(void* const* d_in, const int* in_sizes, int n_in,
                              void* d_out, int out_size)
{
    const float4* ue   = (const float4*)d_in[0];
    const float4* ie   = (const float4*)d_in[1];
    const float*  vals = (const float*)d_in[2];
    const int*    rows = (const int*)d_in[3];
    const int*    cols = (const int*)d_in[4];
    const int*    uidx = (const int*)d_in[5];
    const int*    iidx = (const int*)d_in[6];
    float*        out  = (float*)d_out;

    float4 *x1, *x2, *x3;
    cudaGetSymbolAddress((void**)&x1, g_x1);
    cudaGetSymbolAddress((void**)&x2, g_x2);
    cudaGetSymbolAddress((void**)&x3, g_x3);

    const size_t total = (size_t)NNODES * 16;
    const int eb = (int)((total + 255) / 256);
    const int sblocks = NNZ_C / 64;   // 156250, exact

    init_kernel<<<eb, 256>>>();
    mask_set_kernel<<<(2 * BATCH + 255) / 256, 256>>>(uidx, iidx);

    spmm_l1_kernel<<<sblocks, 256>>>(ue, ie, x1, vals, rows, cols);
    spmm_kernel<<<sblocks, 256>>>(x1, x2, vals, rows, cols);
    spmm_masked_kernel<<<sblocks, 256>>>(x2, x3, vals, rows, cols);

    dot_kernel<<<BATCH / 8, 256>>>((const float*)ue, (const float*)ie,
                                   uidx, iidx, out);
}